// round 7
// baseline (speedup 1.0000x reference)
#include <cuda_runtime.h>
#include <cuda_fp16.h>
#include <cstdint>

// Problem constants: B=2, S=1024, D=2048, F=8192, E=4, K=2
#define TT 2048
#define TD 2048
#define TF 8192
#define TE 4
#define NA 4096

#define KC 64           // K per stage
#define NSTG 3

// GEMM1 smem (halfs/stage): A[128][72] + G[64][72] + U[64][72]
#define G1_STGH (128*72 + 64*72 + 64*72)    // 18432 halfs = 36864 B
#define G1_GB (128*72)                       // 9216
#define G1_UB (128*72 + 64*72)               // 13824
#define G1_SMEM (G1_STGH*NSTG*2 + 512)

// GEMM2 smem (halfs/stage): A[64][72] + B[64][136]
#define G2_STGH (64*72 + 64*136)             // 13312 halfs = 26624 B
#define G2_BB (64*72)                        // 4608
#define G2_SMEM (G2_STGH*NSTG*2)

#define NX4 (TT*TD/4)
#define NW4 (TE*TD*TF/4)

// ---------------- device scratch ----------------
__device__ int    g_counts[TE];
__device__ int    g_fill[TE];
__device__ int    g_offs[TE + 1];
__device__ int    g_eidx[NA];
__device__ float  g_gate[NA];
__device__ int    g_rowmap[NA];
__device__ float  g_rowgate[NA];
__device__ __half g_Xh[(size_t)TT * TD];
__device__ __half g_Wgh[(size_t)TE * TD * TF];
__device__ __half g_Wuh[(size_t)TE * TD * TF];
__device__ __half g_Wdh[(size_t)TE * TF * TD];
__device__ __half g_Hh[(size_t)NA * TF];
__device__ float  g_Y[(size_t)NA * TD];

// ---------------- helpers ----------------
__device__ __forceinline__ uint32_t smem_u32(const void* p) {
    uint32_t a;
    asm("{ .reg .u64 t; cvta.to.shared.u64 t, %1; cvt.u32.u64 %0, t; }" : "=r"(a) : "l"(p));
    return a;
}
__device__ __forceinline__ void cpa16(uint32_t dst, const void* src, uint32_t valid) {
    asm volatile("cp.async.cg.shared.global [%0], [%1], 16, %2;" :: "r"(dst), "l"(src), "r"(valid) : "memory");
}
__device__ __forceinline__ void cpa_commit() { asm volatile("cp.async.commit_group;" ::: "memory"); }
__device__ __forceinline__ void cpa_wait1()  { asm volatile("cp.async.wait_group 1;" ::: "memory"); }

__device__ __forceinline__ void ldmx4(uint32_t* r, uint32_t addr) {
    asm volatile("ldmatrix.sync.aligned.m8n8.x4.shared.b16 {%0,%1,%2,%3}, [%4];"
                 : "=r"(r[0]), "=r"(r[1]), "=r"(r[2]), "=r"(r[3]) : "r"(addr));
}
__device__ __forceinline__ void ldmx4t(uint32_t* r, uint32_t addr) {
    asm volatile("ldmatrix.sync.aligned.m8n8.x4.trans.shared.b16 {%0,%1,%2,%3}, [%4];"
                 : "=r"(r[0]), "=r"(r[1]), "=r"(r[2]), "=r"(r[3]) : "r"(addr));
}
__device__ __forceinline__ void mma_f16(float* c, const uint32_t* a, uint32_t b0, uint32_t b1) {
    asm volatile(
        "mma.sync.aligned.m16n8k16.row.col.f32.f16.f16.f32 "
        "{%0,%1,%2,%3}, {%4,%5,%6,%7}, {%8,%9}, {%0,%1,%2,%3};"
        : "+f"(c[0]), "+f"(c[1]), "+f"(c[2]), "+f"(c[3])
        : "r"(a[0]), "r"(a[1]), "r"(a[2]), "r"(a[3]), "r"(b0), "r"(b1));
}

// ---------------- routing ----------------
__global__ void zero_kernel() {
    int i = threadIdx.x;
    if (i < TE) { g_counts[i] = 0; g_fill[i] = 0; }
}

__global__ void router_kernel(const float* __restrict__ x, const float* __restrict__ Wr) {
    int gw   = (int)((blockIdx.x * blockDim.x + threadIdx.x) >> 5);
    int lane = threadIdx.x & 31;
    if (gw >= TT) return;
    const float* xr = x + (size_t)gw * TD;
    float a0 = 0.f, a1 = 0.f, a2 = 0.f, a3 = 0.f;
    for (int d = lane; d < TD; d += 32) {
        float xv = xr[d];
        float4 w = *(const float4*)(Wr + d * 4);
        a0 += xv * w.x; a1 += xv * w.y; a2 += xv * w.z; a3 += xv * w.w;
    }
    #pragma unroll
    for (int o = 16; o; o >>= 1) {
        a0 += __shfl_xor_sync(0xffffffffu, a0, o);
        a1 += __shfl_xor_sync(0xffffffffu, a1, o);
        a2 += __shfl_xor_sync(0xffffffffu, a2, o);
        a3 += __shfl_xor_sync(0xffffffffu, a3, o);
    }
    if (lane == 0) {
        float l[4] = {a0, a1, a2, a3};
        float m = fmaxf(fmaxf(l[0], l[1]), fmaxf(l[2], l[3]));
        float p[4]; float s = 0.f;
        #pragma unroll
        for (int i = 0; i < 4; i++) { p[i] = __expf(l[i] - m); s += p[i]; }
        float inv = 1.0f / s;
        int i0 = 0;
        #pragma unroll
        for (int i = 1; i < 4; i++) if (p[i] > p[i0]) i0 = i;
        int i1 = (i0 == 0) ? 1 : 0;
        #pragma unroll
        for (int i = 0; i < 4; i++) if (i != i0 && p[i] > p[i1]) i1 = i;
        g_eidx[gw * 2]     = i0; g_gate[gw * 2]     = p[i0] * inv;
        g_eidx[gw * 2 + 1] = i1; g_gate[gw * 2 + 1] = p[i1] * inv;
        atomicAdd(&g_counts[i0], 1);
        atomicAdd(&g_counts[i1], 1);
    }
}

__global__ void offsets_kernel() {
    if (threadIdx.x == 0) {
        int s = 0;
        for (int e = 0; e < TE; e++) { g_offs[e] = s; s += g_counts[e]; }
        g_offs[TE] = s;
    }
}

__global__ void scatter_kernel() {
    int a = blockIdx.x * blockDim.x + threadIdx.x;
    if (a >= NA) return;
    int e = g_eidx[a];
    int pos = g_offs[e] + atomicAdd(&g_fill[e], 1);
    g_rowmap[pos]  = a;
    g_rowgate[pos] = g_gate[a];
}

// ---------------- prep: merged fp32 -> fp16 conversion ----------------
__global__ void cvt_all_kernel(const float4* __restrict__ x, const float4* __restrict__ Wg,
                               const float4* __restrict__ Wu, const float4* __restrict__ Wd) {
    size_t i = (size_t)blockIdx.x * blockDim.x + threadIdx.x;
    const float4* s;
    uint2* d;
    if (i < NX4) { s = x + i; d = (uint2*)g_Xh + i; }
    else if (i < NX4 + (size_t)NW4)       { size_t j = i - NX4;                 s = Wg + j; d = (uint2*)g_Wgh + j; }
    else if (i < NX4 + 2 * (size_t)NW4)   { size_t j = i - NX4 - (size_t)NW4;   s = Wu + j; d = (uint2*)g_Wuh + j; }
    else if (i < NX4 + 3 * (size_t)NW4)   { size_t j = i - NX4 - 2*(size_t)NW4; s = Wd + j; d = (uint2*)g_Wdh + j; }
    else return;
    float4 v = *s;
    __half2 lo = __floats2half2_rn(v.x, v.y);
    __half2 hi = __floats2half2_rn(v.z, v.w);
    uint2 o;
    o.x = *(uint32_t*)&lo;
    o.y = *(uint32_t*)&hi;
    *d = o;
}

// ---------------- GEMM1: H = silu(Xe*Wg) * (Xe*Wu)  [fp16 m16n8k16] ----------------
// CTA tile: M=128 x N=64 (G and U). 8 warps (4m x 2n), warp tile 32x32 each. KC=64, 3 stages.
__global__ __launch_bounds__(256, 2) void gemm1_kernel() {
    const int e    = blockIdx.z;
    const int cnt  = g_counts[e];
    const int row0 = blockIdx.x * 128;
    if (row0 >= cnt) return;
    const int seg = g_offs[e];
    const int f0  = blockIdx.y * 64;

    extern __shared__ __half sm[];
    int* rid = (int*)(sm + G1_STGH * NSTG);

    const int tid = threadIdx.x, lane = tid & 31, warp = tid >> 5;
    const int grp = lane >> 2, t4 = lane & 3;

    if (tid < 128) {
        int r = row0 + tid;
        rid[tid] = (r < cnt) ? (g_rowmap[seg + r] >> 1) : -1;
    }
    __syncthreads();

    // loaders: A 4 chunks, G 2, U 2 per thread per stage
    const int arow = tid >> 1, ah0 = (tid & 1) * 32;
    const int tok  = rid[arow];
    const uint32_t aval = (tok >= 0) ? 16u : 0u;
    const __half* aptr = g_Xh + (size_t)(tok < 0 ? 0 : tok) * TD + ah0;
    const int krow = tid >> 2, gc0 = (tid & 3) * 16;
    const __half* gptr = g_Wgh + ((size_t)e * TD + krow) * TF + f0 + gc0;
    const __half* uptr = g_Wuh + ((size_t)e * TD + krow) * TF + f0 + gc0;

    const uint32_t smb  = smem_u32(sm);
    const uint32_t aoff = smb + arow * 144 + ah0 * 2;
    const uint32_t goff = smb + G1_GB * 2 + krow * 144 + gc0 * 2;
    const uint32_t uoff = smb + G1_UB * 2 + krow * 144 + gc0 * 2;
    const uint32_t SSB = G1_STGH * 2;

    #pragma unroll
    for (int s = 0; s < NSTG - 1; s++) {
        int kb = s * KC;
        #pragma unroll
        for (int j = 0; j < 4; j++) cpa16(aoff + s * SSB + j * 16, aptr + kb + j * 8, aval);
        #pragma unroll
        for (int c = 0; c < 2; c++) {
            cpa16(goff + s * SSB + c * 16, gptr + (size_t)kb * TF + c * 8, 16u);
            cpa16(uoff + s * SSB + c * 16, uptr + (size_t)kb * TF + c * 8, 16u);
        }
        cpa_commit();
    }

    float accG[2][4][4], accU[2][4][4];
    #pragma unroll
    for (int i = 0; i < 2; i++)
        #pragma unroll
        for (int j = 0; j < 4; j++)
            #pragma unroll
            for (int q = 0; q < 4; q++) { accG[i][j][q] = 0.f; accU[i][j][q] = 0.f; }

    const int mrow0 = (warp & 3) * 32;
    const int ncol0 = (warp >> 2) * 32;
    const int aR = mrow0 + ((lane >> 3) & 1) * 8 + (lane & 7);
    const int aC = (lane >> 4) * 8;
    const int bR = ((lane >> 3) & 1) * 8 + (lane & 7);
    const int bC = ncol0 + (lane >> 4) * 8;

    const int NC = TD / KC;   // 32
    #pragma unroll 1
    for (int i = 0; i < NC; i++) {
        cpa_wait1();
        __syncthreads();
        {
            int s = (i + NSTG - 1) % NSTG;
            int kb = (i + NSTG - 1) * KC;
            if (kb < TD) {
                #pragma unroll
                for (int j = 0; j < 4; j++) cpa16(aoff + s * SSB + j * 16, aptr + kb + j * 8, aval);
                #pragma unroll
                for (int c = 0; c < 2; c++) {
                    cpa16(goff + s * SSB + c * 16, gptr + (size_t)kb * TF + c * 8, 16u);
                    cpa16(uoff + s * SSB + c * 16, uptr + (size_t)kb * TF + c * 8, 16u);
                }
            }
            cpa_commit();
        }
        const uint32_t sbase = smb + (i % NSTG) * SSB;
        #pragma unroll
        for (int ks = 0; ks < 4; ks++) {
            uint32_t a[2][4];
            #pragma unroll
            for (int mi = 0; mi < 2; mi++)
                ldmx4(a[mi], sbase + (aR + mi * 16) * 144 + (aC + ks * 16) * 2);
            uint32_t bg[2][4], bu[2][4];
            #pragma unroll
            for (int p = 0; p < 2; p++) {
                uint32_t ro = (bR + ks * 16) * 144 + (bC + p * 16) * 2;
                ldmx4t(bg[p], sbase + G1_GB * 2 + ro);
                ldmx4t(bu[p], sbase + G1_UB * 2 + ro);
            }
            #pragma unroll
            for (int p = 0; p < 2; p++)
                #pragma unroll
                for (int sub = 0; sub < 2; sub++) {
                    const int ni = p * 2 + sub;
                    #pragma unroll
                    for (int mi = 0; mi < 2; mi++) {
                        mma_f16(accG[mi][ni], a[mi], bg[p][sub * 2], bg[p][sub * 2 + 1]);
                        mma_f16(accU[mi][ni], a[mi], bu[p][sub * 2], bu[p][sub * 2 + 1]);
                    }
                }
        }
    }

    // epilogue: h = silu(g)*u -> g_Hh (fp16)
    #pragma unroll
    for (int mi = 0; mi < 2; mi++) {
        const int rl = (warp & 3) * 32 + mi * 16 + grp;
        const int r0 = row0 + rl, r1 = row0 + rl + 8;
        #pragma unroll
        for (int ni = 0; ni < 4; ni++) {
            const int col = f0 + (warp >> 2) * 32 + ni * 8 + t4 * 2;
            if (r0 < cnt) {
                float gg0 = accG[mi][ni][0], uu0 = accU[mi][ni][0];
                float gg1 = accG[mi][ni][1], uu1 = accU[mi][ni][1];
                float h0 = __fdividef(gg0 * uu0, 1.0f + __expf(-gg0));
                float h1 = __fdividef(gg1 * uu1, 1.0f + __expf(-gg1));
                *(__half2*)&g_Hh[(size_t)(seg + r0) * TF + col] = __floats2half2_rn(h0, h1);
            }
            if (r1 < cnt) {
                float gg0 = accG[mi][ni][2], uu0 = accU[mi][ni][2];
                float gg1 = accG[mi][ni][3], uu1 = accU[mi][ni][3];
                float h0 = __fdividef(gg0 * uu0, 1.0f + __expf(-gg0));
                float h1 = __fdividef(gg1 * uu1, 1.0f + __expf(-gg1));
                *(__half2*)&g_Hh[(size_t)(seg + r1) * TF + col] = __floats2half2_rn(h0, h1);
            }
        }
    }
}

// ---------------- GEMM2: Y = gate * (H * Wd)  [fp16 m16n8k16] ----------------
// CTA tile: M=64 x N=128. 8 warps (2m x 4n), warp tile 32x32. KC=64, 3 stages.
__global__ __launch_bounds__(256, 2) void gemm2_kernel() {
    const int e    = blockIdx.z;
    const int cnt  = g_counts[e];
    const int row0 = blockIdx.x * 64;
    if (row0 >= cnt) return;
    const int seg = g_offs[e];
    const int n0  = blockIdx.y * 128;

    extern __shared__ __half sm[];
    const int tid = threadIdx.x, lane = tid & 31, warp = tid >> 5;
    const int grp = lane >> 2, t4 = lane & 3;

    // loaders: A 2 chunks, B 4 chunks per thread per stage
    const int arow = tid >> 2, ac0 = (tid & 3) * 16;
    const uint32_t aval = (row0 + arow < cnt) ? 16u : 0u;
    const __half* aptr = g_Hh + (size_t)(seg + ((row0 + arow < cnt) ? row0 + arow : 0)) * TF + ac0;
    const int krow = tid >> 2, bc0 = (tid & 3) * 32;
    const __half* bptr = g_Wdh + ((size_t)e * TF + krow) * TD + n0 + bc0;

    const uint32_t smb  = smem_u32(sm);
    const uint32_t aoff = smb + arow * 144 + ac0 * 2;
    const uint32_t boff = smb + G2_BB * 2 + krow * 272 + bc0 * 2;
    const uint32_t SSB = G2_STGH * 2;

    #pragma unroll
    for (int s = 0; s < NSTG - 1; s++) {
        int kb = s * KC;
        #pragma unroll
        for (int c = 0; c < 2; c++) cpa16(aoff + s * SSB + c * 16, aptr + kb + c * 8, aval);
        #pragma unroll
        for (int c = 0; c < 4; c++) cpa16(boff + s * SSB + c * 16, bptr + (size_t)kb * TD + c * 8, 16u);
        cpa_commit();
    }

    float acc[2][4][4];
    #pragma unroll
    for (int i = 0; i < 2; i++)
        #pragma unroll
        for (int j = 0; j < 4; j++)
            #pragma unroll
            for (int q = 0; q < 4; q++) acc[i][j][q] = 0.f;

    const int mrow0 = (warp & 1) * 32;
    const int ncol0 = (warp >> 1) * 32;
    const int aR = mrow0 + ((lane >> 3) & 1) * 8 + (lane & 7);
    const int aC = (lane >> 4) * 8;
    const int bR = ((lane >> 3) & 1) * 8 + (lane & 7);
    const int bC = ncol0 + (lane >> 4) * 8;

    const int NC = TF / KC;   // 128
    #pragma unroll 1
    for (int i = 0; i < NC; i++) {
        cpa_wait1();
        __syncthreads();
        {
            int s = (i + NSTG - 1) % NSTG;
            int kb = (i + NSTG - 1) * KC;
            if (kb < TF) {
                #pragma unroll
                for (int c = 0; c < 2; c++) cpa16(aoff + s * SSB + c * 16, aptr + kb + c * 8, aval);
                #pragma unroll
                for (int c = 0; c < 4; c++) cpa16(boff + s * SSB + c * 16, bptr + (size_t)kb * TD + c * 8, 16u);
            }
            cpa_commit();
        }
        const uint32_t sbase = smb + (i % NSTG) * SSB;
        #pragma unroll
        for (int ks = 0; ks < 4; ks++) {
            uint32_t a[2][4];
            #pragma unroll
            for (int mi = 0; mi < 2; mi++)
                ldmx4(a[mi], sbase + (aR + mi * 16) * 144 + (aC + ks * 16) * 2);
            #pragma unroll
            for (int p = 0; p < 2; p++) {
                uint32_t bb[4];
                ldmx4t(bb, sbase + G2_BB * 2 + (bR + ks * 16) * 272 + (bC + p * 16) * 2);
                #pragma unroll
                for (int sub = 0; sub < 2; sub++) {
                    const int ni = p * 2 + sub;
                    #pragma unroll
                    for (int mi = 0; mi < 2; mi++)
                        mma_f16(acc[mi][ni], a[mi], bb[sub * 2], bb[sub * 2 + 1]);
                }
            }
        }
    }

    // epilogue: scale by gate, scatter to assignment slot (fp32)
    #pragma unroll
    for (int mi = 0; mi < 2; mi++) {
        const int rl = (warp & 1) * 32 + mi * 16 + grp;
        const int r0 = row0 + rl, r1 = row0 + rl + 8;
        int a0i = 0, a1i = 0; float w0 = 0.f, w1 = 0.f;
        if (r0 < cnt) { a0i = g_rowmap[seg + r0]; w0 = g_rowgate[seg + r0]; }
        if (r1 < cnt) { a1i = g_rowmap[seg + r1]; w1 = g_rowgate[seg + r1]; }
        #pragma unroll
        for (int ni = 0; ni < 4; ni++) {
            const int col = n0 + (warp >> 1) * 32 + ni * 8 + t4 * 2;
            if (r0 < cnt) {
                float2 v; v.x = w0 * acc[mi][ni][0]; v.y = w0 * acc[mi][ni][1];
                *(float2*)&g_Y[(size_t)a0i * TD + col] = v;
            }
            if (r1 < cnt) {
                float2 v; v.x = w1 * acc[mi][ni][2]; v.y = w1 * acc[mi][ni][3];
                *(float2*)&g_Y[(size_t)a1i * TD + col] = v;
            }
        }
    }
}

// ---------------- combine ----------------
__global__ void combine_kernel(float* __restrict__ out) {
    int i = blockIdx.x * blockDim.x + threadIdx.x;
    if (i >= TT * TD) return;
    int t = i >> 11;
    int d = i & (TD - 1);
    out[i] = g_Y[(size_t)(2 * t) * TD + d] + g_Y[(size_t)(2 * t + 1) * TD + d];
}

// ---------------- launch ----------------
extern "C" void kernel_launch(void* const* d_in, const int* in_sizes, int n_in,
                              void* d_out, int out_size) {
    const float* x  = (const float*)d_in[0];
    const float* Wr = (const float*)d_in[1];
    const float* Wg = (const float*)d_in[2];
    const float* Wu = (const float*)d_in[3];
    const float* Wd = (const float*)d_in[4];
    float* out = (float*)d_out;

    static int attr_done = 0;
    if (!attr_done) {
        cudaFuncSetAttribute(gemm1_kernel, cudaFuncAttributeMaxDynamicSharedMemorySize, G1_SMEM);
        cudaFuncSetAttribute(gemm2_kernel, cudaFuncAttributeMaxDynamicSharedMemorySize, G2_SMEM);
        attr_done = 1;
    }

    zero_kernel<<<1, 32>>>();
    router_kernel<<<TT / 8, 256>>>(x, Wr);
    offsets_kernel<<<1, 1>>>();
    scatter_kernel<<<NA / 256, 256>>>();

    {
        size_t total = (size_t)NX4 + 3 * (size_t)NW4;
        cvt_all_kernel<<<(unsigned)((total + 255) / 256), 256>>>(
            (const float4*)x, (const float4*)Wg, (const float4*)Wu, (const float4*)Wd);
    }

    gemm1_kernel<<<dim3(16, TF / 64, TE), 256, G1_SMEM>>>();
    gemm2_kernel<<<dim3(32, TD / 128, TE), 256, G2_SMEM>>>();

    combine_kernel<<<(TT * TD) / 256, 256>>>(out);
}

// round 8
// speedup vs baseline: 1.2153x; 1.2153x over previous
#include <cuda_runtime.h>
#include <cuda_fp16.h>
#include <cstdint>

// Problem constants: B=2, S=1024, D=2048, F=8192, E=4, K=2
#define TT 2048
#define TD 2048
#define TF 8192
#define TE 4
#define NA 4096

#define KC 32           // K per stage (fp16)
#define NSTG 4

// GEMM1 smem (halfs/stage): A[128][40] + G[32][72] + U[32][72]
#define G1_STGH (128*40 + 32*72 + 32*72)    // 9728 halfs = 19456 B
#define G1_GB (128*40)                      // 5120
#define G1_UB (128*40 + 32*72)              // 7424
#define G1_SMEM (G1_STGH*NSTG*2 + 512)

// GEMM2 smem (halfs/stage): A[128][40] + B0[32][72] + B1[32][72]
#define G2_STGH G1_STGH
#define G2_B0 (128*40)
#define G2_B1 (128*40 + 32*72)
#define G2_SMEM (G2_STGH*NSTG*2)

#define NX4 (TT*TD/4)
#define NW4 (TE*TD*TF/4)

// ---------------- device scratch ----------------
__device__ int    g_counts[TE];
__device__ int    g_fill[TE];
__device__ int    g_offs[TE + 1];
__device__ int    g_eidx[NA];
__device__ float  g_gate[NA];
__device__ int    g_rowmap[NA];
__device__ float  g_rowgate[NA];
__device__ __half g_Xh[(size_t)TT * TD];
__device__ __half g_Wgh[(size_t)TE * TD * TF];
__device__ __half g_Wuh[(size_t)TE * TD * TF];
__device__ __half g_Wdh[(size_t)TE * TF * TD];
__device__ __half g_Hh[(size_t)NA * TF];
__device__ float  g_Y0[(size_t)NA * TD];    // split-K slice 0
__device__ float  g_Y1[(size_t)NA * TD];    // split-K slice 1

// ---------------- helpers ----------------
__device__ __forceinline__ uint32_t smem_u32(const void* p) {
    uint32_t a;
    asm("{ .reg .u64 t; cvta.to.shared.u64 t, %1; cvt.u32.u64 %0, t; }" : "=r"(a) : "l"(p));
    return a;
}
__device__ __forceinline__ void cpa16(uint32_t dst, const void* src, uint32_t valid) {
    asm volatile("cp.async.cg.shared.global [%0], [%1], 16, %2;" :: "r"(dst), "l"(src), "r"(valid) : "memory");
}
__device__ __forceinline__ void cpa_commit() { asm volatile("cp.async.commit_group;" ::: "memory"); }
__device__ __forceinline__ void cpa_wait2()  { asm volatile("cp.async.wait_group 2;" ::: "memory"); }

__device__ __forceinline__ void ldmx4(uint32_t* r, uint32_t addr) {
    asm volatile("ldmatrix.sync.aligned.m8n8.x4.shared.b16 {%0,%1,%2,%3}, [%4];"
                 : "=r"(r[0]), "=r"(r[1]), "=r"(r[2]), "=r"(r[3]) : "r"(addr));
}
__device__ __forceinline__ void ldmx4t(uint32_t* r, uint32_t addr) {
    asm volatile("ldmatrix.sync.aligned.m8n8.x4.trans.shared.b16 {%0,%1,%2,%3}, [%4];"
                 : "=r"(r[0]), "=r"(r[1]), "=r"(r[2]), "=r"(r[3]) : "r"(addr));
}
__device__ __forceinline__ void mma_f16(float* c, const uint32_t* a, uint32_t b0, uint32_t b1) {
    asm volatile(
        "mma.sync.aligned.m16n8k16.row.col.f32.f16.f16.f32 "
        "{%0,%1,%2,%3}, {%4,%5,%6,%7}, {%8,%9}, {%0,%1,%2,%3};"
        : "+f"(c[0]), "+f"(c[1]), "+f"(c[2]), "+f"(c[3])
        : "r"(a[0]), "r"(a[1]), "r"(a[2]), "r"(a[3]), "r"(b0), "r"(b1));
}

// ---------------- routing ----------------
__global__ void zero_kernel() {
    int i = threadIdx.x;
    if (i < TE) { g_counts[i] = 0; g_fill[i] = 0; }
}

__global__ void router_kernel(const float* __restrict__ x, const float* __restrict__ Wr) {
    int gw   = (int)((blockIdx.x * blockDim.x + threadIdx.x) >> 5);
    int lane = threadIdx.x & 31;
    if (gw >= TT) return;
    const float* xr = x + (size_t)gw * TD;
    float a0 = 0.f, a1 = 0.f, a2 = 0.f, a3 = 0.f;
    for (int d = lane; d < TD; d += 32) {
        float xv = xr[d];
        float4 w = *(const float4*)(Wr + d * 4);
        a0 += xv * w.x; a1 += xv * w.y; a2 += xv * w.z; a3 += xv * w.w;
    }
    #pragma unroll
    for (int o = 16; o; o >>= 1) {
        a0 += __shfl_xor_sync(0xffffffffu, a0, o);
        a1 += __shfl_xor_sync(0xffffffffu, a1, o);
        a2 += __shfl_xor_sync(0xffffffffu, a2, o);
        a3 += __shfl_xor_sync(0xffffffffu, a3, o);
    }
    if (lane == 0) {
        float l[4] = {a0, a1, a2, a3};
        float m = fmaxf(fmaxf(l[0], l[1]), fmaxf(l[2], l[3]));
        float p[4]; float s = 0.f;
        #pragma unroll
        for (int i = 0; i < 4; i++) { p[i] = __expf(l[i] - m); s += p[i]; }
        float inv = 1.0f / s;
        int i0 = 0;
        #pragma unroll
        for (int i = 1; i < 4; i++) if (p[i] > p[i0]) i0 = i;
        int i1 = (i0 == 0) ? 1 : 0;
        #pragma unroll
        for (int i = 0; i < 4; i++) if (i != i0 && p[i] > p[i1]) i1 = i;
        g_eidx[gw * 2]     = i0; g_gate[gw * 2]     = p[i0] * inv;
        g_eidx[gw * 2 + 1] = i1; g_gate[gw * 2 + 1] = p[i1] * inv;
        atomicAdd(&g_counts[i0], 1);
        atomicAdd(&g_counts[i1], 1);
    }
}

__global__ void offsets_kernel() {
    if (threadIdx.x == 0) {
        int s = 0;
        for (int e = 0; e < TE; e++) { g_offs[e] = s; s += g_counts[e]; }
        g_offs[TE] = s;
    }
}

__global__ void scatter_kernel() {
    int a = blockIdx.x * blockDim.x + threadIdx.x;
    if (a >= NA) return;
    int e = g_eidx[a];
    int pos = g_offs[e] + atomicAdd(&g_fill[e], 1);
    g_rowmap[pos]  = a;
    g_rowgate[pos] = g_gate[a];
}

// ---------------- prep: merged fp32 -> fp16 conversion ----------------
__global__ void cvt_all_kernel(const float4* __restrict__ x, const float4* __restrict__ Wg,
                               const float4* __restrict__ Wu, const float4* __restrict__ Wd) {
    size_t i = (size_t)blockIdx.x * blockDim.x + threadIdx.x;
    const float4* s;
    uint2* d;
    if (i < NX4) { s = x + i; d = (uint2*)g_Xh + i; }
    else if (i < NX4 + (size_t)NW4)       { size_t j = i - NX4;                 s = Wg + j; d = (uint2*)g_Wgh + j; }
    else if (i < NX4 + 2 * (size_t)NW4)   { size_t j = i - NX4 - (size_t)NW4;   s = Wu + j; d = (uint2*)g_Wuh + j; }
    else if (i < NX4 + 3 * (size_t)NW4)   { size_t j = i - NX4 - 2*(size_t)NW4; s = Wd + j; d = (uint2*)g_Wdh + j; }
    else return;
    float4 v = *s;
    __half2 lo = __floats2half2_rn(v.x, v.y);
    __half2 hi = __floats2half2_rn(v.z, v.w);
    uint2 o;
    o.x = *(uint32_t*)&lo;
    o.y = *(uint32_t*)&hi;
    *d = o;
}

// ---------------- GEMM1: H = silu(Xe*Wg) * (Xe*Wu)  [fp16 m16n8k16] ----------------
// CTA tile: M=128 x N=64 (both G and U). 8 warps (4m x 2n), warp tile 32x32 each.
__global__ __launch_bounds__(256, 2) void gemm1_kernel() {
    const int e    = blockIdx.z;
    const int cnt  = g_counts[e];
    const int row0 = blockIdx.x * 128;
    if (row0 >= cnt) return;
    const int seg = g_offs[e];
    const int f0  = blockIdx.y * 64;

    extern __shared__ __half sm[];
    int* rid = (int*)(sm + G1_STGH * NSTG);

    const int tid = threadIdx.x, lane = tid & 31, warp = tid >> 5;
    const int grp = lane >> 2, t4 = lane & 3;

    if (tid < 128) {
        int r = row0 + tid;
        rid[tid] = (r < cnt) ? (g_rowmap[seg + r] >> 1) : -1;
    }
    __syncthreads();

    // loaders
    const int arow = tid >> 1, ach = (tid & 1);        // A: 2 x 16B
    const int tok  = rid[arow];
    const uint32_t aval = (tok >= 0) ? 16u : 0u;
    const __half* aptr = g_Xh + (size_t)(tok < 0 ? 0 : tok) * TD + ach * 16;
    const int krow = tid >> 3, nc = tid & 7;           // G/U: 1 x 16B each
    const __half* gptr = g_Wgh + ((size_t)e * TD + krow) * TF + f0 + nc * 8;
    const __half* uptr = g_Wuh + ((size_t)e * TD + krow) * TF + f0 + nc * 8;

    const uint32_t smb = smem_u32(sm);
    const uint32_t aoff = smb + arow * 80 + ach * 32;
    const uint32_t goff = smb + G1_GB * 2 + krow * 144 + nc * 16;
    const uint32_t uoff = smb + G1_UB * 2 + krow * 144 + nc * 16;
    const uint32_t SSB = G1_STGH * 2;

    #pragma unroll
    for (int s = 0; s < NSTG - 1; s++) {
        int kb = s * KC;
        cpa16(aoff + s * SSB,      aptr + kb,     aval);
        cpa16(aoff + s * SSB + 16, aptr + kb + 8, aval);
        cpa16(goff + s * SSB, gptr + (size_t)kb * TF, 16u);
        cpa16(uoff + s * SSB, uptr + (size_t)kb * TF, 16u);
        cpa_commit();
    }

    float accG[2][4][4], accU[2][4][4];
    #pragma unroll
    for (int i = 0; i < 2; i++)
        #pragma unroll
        for (int j = 0; j < 4; j++)
            #pragma unroll
            for (int q = 0; q < 4; q++) { accG[i][j][q] = 0.f; accU[i][j][q] = 0.f; }

    // ldmatrix lane maps
    const int mrow0 = (warp & 3) * 32;
    const int ncol0 = (warp >> 2) * 32;
    const int aR = mrow0 + ((lane >> 3) & 1) * 8 + (lane & 7);   // + mi*16
    const int aC = (lane >> 4) * 8;                              // + ks*16
    const int bR = ((lane >> 3) & 1) * 8 + (lane & 7);           // + ks*16 (k dir)
    const int bC = ncol0 + (lane >> 4) * 8;                      // + pair*16

    const int NC = TD / KC;   // 64
    #pragma unroll 1
    for (int i = 0; i < NC; i++) {
        cpa_wait2();
        __syncthreads();
        {
            int s = (i + NSTG - 1) & 3;
            int kb = (i + NSTG - 1) * KC;
            if (kb < TD) {
                cpa16(aoff + s * SSB,      aptr + kb,     aval);
                cpa16(aoff + s * SSB + 16, aptr + kb + 8, aval);
                cpa16(goff + s * SSB, gptr + (size_t)kb * TF, 16u);
                cpa16(uoff + s * SSB, uptr + (size_t)kb * TF, 16u);
            }
            cpa_commit();
        }
        const uint32_t sbase = smb + (i & 3) * SSB;
        #pragma unroll
        for (int ks = 0; ks < 2; ks++) {
            uint32_t a[2][4];
            #pragma unroll
            for (int mi = 0; mi < 2; mi++)
                ldmx4(a[mi], sbase + (aR + mi * 16) * 80 + (aC + ks * 16) * 2);
            uint32_t bg[2][4], bu[2][4];
            #pragma unroll
            for (int p = 0; p < 2; p++) {
                uint32_t ro = (bR + ks * 16) * 144 + (bC + p * 16) * 2;
                ldmx4t(bg[p], sbase + G1_GB * 2 + ro);
                ldmx4t(bu[p], sbase + G1_UB * 2 + ro);
            }
            #pragma unroll
            for (int p = 0; p < 2; p++)
                #pragma unroll
                for (int sub = 0; sub < 2; sub++) {
                    const int ni = p * 2 + sub;
                    #pragma unroll
                    for (int mi = 0; mi < 2; mi++) {
                        mma_f16(accG[mi][ni], a[mi], bg[p][sub * 2], bg[p][sub * 2 + 1]);
                        mma_f16(accU[mi][ni], a[mi], bu[p][sub * 2], bu[p][sub * 2 + 1]);
                    }
                }
        }
    }

    // epilogue: h = silu(g)*u -> g_Hh (fp16)
    #pragma unroll
    for (int mi = 0; mi < 2; mi++) {
        const int rl = (warp & 3) * 32 + mi * 16 + grp;
        const int r0 = row0 + rl, r1 = row0 + rl + 8;
        #pragma unroll
        for (int ni = 0; ni < 4; ni++) {
            const int col = f0 + (warp >> 2) * 32 + ni * 8 + t4 * 2;
            if (r0 < cnt) {
                float gg0 = accG[mi][ni][0], uu0 = accU[mi][ni][0];
                float gg1 = accG[mi][ni][1], uu1 = accU[mi][ni][1];
                float h0 = __fdividef(gg0 * uu0, 1.0f + __expf(-gg0));
                float h1 = __fdividef(gg1 * uu1, 1.0f + __expf(-gg1));
                *(__half2*)&g_Hh[(size_t)(seg + r0) * TF + col] = __floats2half2_rn(h0, h1);
            }
            if (r1 < cnt) {
                float gg0 = accG[mi][ni][2], uu0 = accU[mi][ni][2];
                float gg1 = accG[mi][ni][3], uu1 = accU[mi][ni][3];
                float h0 = __fdividef(gg0 * uu0, 1.0f + __expf(-gg0));
                float h1 = __fdividef(gg1 * uu1, 1.0f + __expf(-gg1));
                *(__half2*)&g_Hh[(size_t)(seg + r1) * TF + col] = __floats2half2_rn(h0, h1);
            }
        }
    }
}

// ---------------- GEMM2: Y = gate * (H * Wd)  [fp16 m16n8k16, split-K x2] ----------------
// CTA tile: M=128 x N=128, K half = 4096. 8 warps (4m x 2n), warp tile 32x64.
// blockIdx.y encodes (n-panel, kslice): y = npanel*2 + kslice.
__global__ __launch_bounds__(256, 2) void gemm2_kernel() {
    const int e    = blockIdx.z;
    const int cnt  = g_counts[e];
    const int row0 = blockIdx.x * 128;
    if (row0 >= cnt) return;
    const int seg = g_offs[e];
    const int n0  = (blockIdx.y >> 1) * 128;
    const int ksl = blockIdx.y & 1;
    const int k0  = ksl * (TF / 2);
    float* Yout = ksl ? g_Y1 : g_Y0;

    extern __shared__ __half sm[];
    const int tid = threadIdx.x, lane = tid & 31, warp = tid >> 5;
    const int grp = lane >> 2, t4 = lane & 3;

    const int arow = tid >> 1, ach = (tid & 1);
    const uint32_t aval = (row0 + arow < cnt) ? 16u : 0u;
    const __half* aptr = g_Hh + (size_t)(seg + ((row0 + arow < cnt) ? row0 + arow : 0)) * TF + k0 + ach * 16;
    const int krow = tid >> 3, nc = tid & 7;
    const __half* bptr = g_Wdh + ((size_t)e * TF + k0 + krow) * TD + n0 + nc * 8;

    const uint32_t smb = smem_u32(sm);
    const uint32_t aoff = smb + arow * 80 + ach * 32;
    const uint32_t b0off = smb + G2_B0 * 2 + krow * 144 + nc * 16;
    const uint32_t b1off = smb + G2_B1 * 2 + krow * 144 + nc * 16;
    const uint32_t SSB = G2_STGH * 2;

    #pragma unroll
    for (int s = 0; s < NSTG - 1; s++) {
        int kb = s * KC;
        cpa16(aoff + s * SSB,      aptr + kb,     aval);
        cpa16(aoff + s * SSB + 16, aptr + kb + 8, aval);
        cpa16(b0off + s * SSB, bptr + (size_t)kb * TD,      16u);
        cpa16(b1off + s * SSB, bptr + (size_t)kb * TD + 64, 16u);
        cpa_commit();
    }

    float acc[2][8][4];
    #pragma unroll
    for (int i = 0; i < 2; i++)
        #pragma unroll
        for (int j = 0; j < 8; j++)
            #pragma unroll
            for (int q = 0; q < 4; q++) acc[i][j][q] = 0.f;

    const int mrow0 = (warp & 3) * 32;
    const uint32_t sBbase = (warp >> 2) ? (G2_B1 * 2) : (G2_B0 * 2);  // warp n-half
    const int aR = mrow0 + ((lane >> 3) & 1) * 8 + (lane & 7);
    const int aC = (lane >> 4) * 8;
    const int bR = ((lane >> 3) & 1) * 8 + (lane & 7);
    const int bC = (lane >> 4) * 8;                                   // + pair*16 (within 64)

    const int NC = (TF / 2) / KC;   // 128
    #pragma unroll 1
    for (int i = 0; i < NC; i++) {
        cpa_wait2();
        __syncthreads();
        {
            int s = (i + NSTG - 1) & 3;
            int kb = (i + NSTG - 1) * KC;
            if (kb < TF / 2) {
                cpa16(aoff + s * SSB,      aptr + kb,     aval);
                cpa16(aoff + s * SSB + 16, aptr + kb + 8, aval);
                cpa16(b0off + s * SSB, bptr + (size_t)kb * TD,      16u);
                cpa16(b1off + s * SSB, bptr + (size_t)kb * TD + 64, 16u);
            }
            cpa_commit();
        }
        const uint32_t sbase = smb + (i & 3) * SSB;
        #pragma unroll
        for (int ks = 0; ks < 2; ks++) {
            uint32_t a[2][4];
            #pragma unroll
            for (int mi = 0; mi < 2; mi++)
                ldmx4(a[mi], sbase + (aR + mi * 16) * 80 + (aC + ks * 16) * 2);
            #pragma unroll
            for (int p = 0; p < 4; p++) {
                uint32_t bb[4];
                ldmx4t(bb, sbase + sBbase + (bR + ks * 16) * 144 + (bC + p * 16) * 2);
                #pragma unroll
                for (int sub = 0; sub < 2; sub++) {
                    const int ni = p * 2 + sub;
                    #pragma unroll
                    for (int mi = 0; mi < 2; mi++)
                        mma_f16(acc[mi][ni], a[mi], bb[sub * 2], bb[sub * 2 + 1]);
                }
            }
        }
    }

    // epilogue: scale by gate, scatter to assignment slot (fp32)
    #pragma unroll
    for (int mi = 0; mi < 2; mi++) {
        const int rl = (warp & 3) * 32 + mi * 16 + grp;
        const int r0 = row0 + rl, r1 = row0 + rl + 8;
        int a0i = 0, a1i = 0; float w0 = 0.f, w1 = 0.f;
        if (r0 < cnt) { a0i = g_rowmap[seg + r0]; w0 = g_rowgate[seg + r0]; }
        if (r1 < cnt) { a1i = g_rowmap[seg + r1]; w1 = g_rowgate[seg + r1]; }
        #pragma unroll
        for (int ni = 0; ni < 8; ni++) {
            const int col = n0 + (warp >> 2) * 64 + ni * 8 + t4 * 2;
            if (r0 < cnt) {
                float2 v; v.x = w0 * acc[mi][ni][0]; v.y = w0 * acc[mi][ni][1];
                *(float2*)&Yout[(size_t)a0i * TD + col] = v;
            }
            if (r1 < cnt) {
                float2 v; v.x = w1 * acc[mi][ni][2]; v.y = w1 * acc[mi][ni][3];
                *(float2*)&Yout[(size_t)a1i * TD + col] = v;
            }
        }
    }
}

// ---------------- combine: out[t] = sum over 2 slots x 2 k-slices ----------------
__global__ void combine_kernel(float* __restrict__ out) {
    int i = blockIdx.x * blockDim.x + threadIdx.x;
    if (i >= TT * TD) return;
    int t = i >> 11;
    int d = i & (TD - 1);
    size_t i0 = (size_t)(2 * t) * TD + d;
    size_t i1 = (size_t)(2 * t + 1) * TD + d;
    out[i] = (g_Y0[i0] + g_Y1[i0]) + (g_Y0[i1] + g_Y1[i1]);
}

// ---------------- launch ----------------
extern "C" void kernel_launch(void* const* d_in, const int* in_sizes, int n_in,
                              void* d_out, int out_size) {
    const float* x  = (const float*)d_in[0];
    const float* Wr = (const float*)d_in[1];
    const float* Wg = (const float*)d_in[2];
    const float* Wu = (const float*)d_in[3];
    const float* Wd = (const float*)d_in[4];
    float* out = (float*)d_out;

    static int attr_done = 0;
    if (!attr_done) {
        cudaFuncSetAttribute(gemm1_kernel, cudaFuncAttributeMaxDynamicSharedMemorySize, G1_SMEM);
        cudaFuncSetAttribute(gemm2_kernel, cudaFuncAttributeMaxDynamicSharedMemorySize, G2_SMEM);
        attr_done = 1;
    }

    zero_kernel<<<1, 32>>>();
    router_kernel<<<TT / 8, 256>>>(x, Wr);
    offsets_kernel<<<1, 1>>>();
    scatter_kernel<<<NA / 256, 256>>>();

    {
        size_t total = (size_t)NX4 + 3 * (size_t)NW4;
        cvt_all_kernel<<<(unsigned)((total + 255) / 256), 256>>>(
            (const float4*)x, (const float4*)Wg, (const float4*)Wu, (const float4*)Wd);
    }

    gemm1_kernel<<<dim3(16, TF / 64, TE), 256, G1_SMEM>>>();
    gemm2_kernel<<<dim3(16, (TD / 128) * 2, TE), 256, G2_SMEM>>>();

    combine_kernel<<<(TT * TD) / 256, 256>>>(out);
}